// round 17
// baseline (speedup 1.0000x reference)
#include <cuda_runtime.h>
#include <cuda_fp16.h>
#include <cstdint>
#include <math.h>

#define NNODES 87381
#define NLEAF  65536

// =================== scratch (device globals; no allocation) =================
// Tiled half2 layout for GEMM A operands (128-row x 16-col chunks):
//   half2 word(row,k2) = base[(rowblk*NCH + chunk)*1024 + (s*128+m)*4 + c4]
//   chunk=k>>4, kk=k&15, s=kk>>3, c4=(kk&7)>>1; word = (k_even, k_odd).
// X path: NCH=20 (K padded 300->320, chunks 19 zero); H path: NCH=10.
__device__ __align__(16) __half g_E2[683u * 20 * 2048];  // fp16 embs, tiled
__device__ __align__(16) __half g_X [88064u * 640];      // x-projections [i|u|o|f]
__device__ __align__(16) __half g_H2[683u * 10 * 2048];  // fp16 h, tiled, 160-pad
__device__ __align__(16) __half g_HS2[128u * 10 * 2048]; // fp16 child-sum, tiled
__device__ float  g_C [NNODES * 150];                    // cell states (fp32)
__device__ __align__(16) __half g_P [16384u * 480];      // parent proj [i|u|o]
__device__ __align__(16) __half g_F [65536u * 160];      // child f-projections
// B operands: [chunk][s][c4][col(640)][parity] halves (rows of 1280 halves)
__device__ __align__(16) __half g_Wxp[20 * 10240];       // Wx packed fp16, 20 chunks
__device__ __align__(16) __half g_Whp[10 * 10240];       // Wh packed fp16
__device__ float g_Wh2[160 * 640];        // Wh plain fp32 for small levels
__device__ float g_bx[640];
__device__ float g_bh[640];

// =================== helpers ==================================================
__device__ __forceinline__ float sigf(float x) {
    return __fdividef(1.0f, 1.0f + __expf(-x));
}
__device__ __forceinline__ float tanh_fast(float x) {
    return __fdividef(2.0f, 1.0f + __expf(-2.0f * x)) - 1.0f;
}
// half-element index of h(row, j) in tiled buffer (NCH = 10)
__device__ __forceinline__ size_t hpos(int row, int j) {
    int rb = row >> 7, m = row & 127;
    int chunk = j >> 4, kk = j & 15;
    int s = kk >> 3, r = kk & 7;
    return ((size_t)(rb * 10 + chunk) << 11) +
           (size_t)((((s << 7) + m) * 4 + (r >> 1)) * 2 + (r & 1));
}
__device__ __forceinline__ void mma16(float* d, const unsigned* a, const unsigned* b) {
    asm volatile(
        "mma.sync.aligned.m16n8k16.row.col.f32.f16.f16.f32 "
        "{%0,%1,%2,%3}, {%4,%5,%6,%7}, {%8,%9}, {%0,%1,%2,%3};\n"
        : "+f"(d[0]), "+f"(d[1]), "+f"(d[2]), "+f"(d[3])
        : "r"(a[0]), "r"(a[1]), "r"(a[2]), "r"(a[3]), "r"(b[0]), "r"(b[1]));
}
__device__ __forceinline__ void cp16(uint32_t dst, const void* src) {
    asm volatile("cp.async.ca.shared.global [%0], [%1], 16;" :: "r"(dst), "l"(src));
}
#define CP_COMMIT() asm volatile("cp.async.commit_group;" ::: "memory")
#define CP_WAIT2()  asm volatile("cp.async.wait_group 2;" ::: "memory")

// =================== prep: embs->tiled fp16 + weight packing =================
__global__ void prep_kernel(const float* __restrict__ embs,
    const float* Wix, const float* bix, const float* Wfx, const float* bfx,
    const float* Wux, const float* bux, const float* Wox, const float* box_,
    const float* Wih, const float* bih, const float* Wfh, const float* bfh,
    const float* Wuh, const float* buh, const float* Woh, const float* boh)
{
    const int TOTE = 683 * 20 * 1024;   // half2 words of E2
    const int T0 = 20 * 10240;          // Wxp halves
    const int T1 = T0 + 10 * 10240;     // Whp halves
    const int T2 = T1 + 160 * 640;      // Wh2 floats
    const int T3 = T2 + 640;            // bx
    const int T4 = T3 + 640;            // bh
    int idx = blockIdx.x * blockDim.x + threadIdx.x;
    if (idx < TOTE) {
        int w2 = idx & 1023, t = idx >> 10;
        int chunk = t % 20, rb = t / 20;
        int c4 = w2 & 3, m = (w2 >> 2) & 127, s = w2 >> 9;
        int row = (rb << 7) + m;
        int k = chunk * 16 + s * 8 + c4 * 2;
        float vx = 0.f, vy = 0.f;
        if (row < NNODES && k < 300) {
            const float* er = embs + (size_t)row * 300;
            vx = er[k];
            if (k + 1 < 300) vy = er[k + 1];
        }
        ((__half2*)g_E2)[idx] = __floats2half2_rn(vx, vy);
        return;
    }
    int p = idx - TOTE;
    if (p >= T4) return;
    if (p < T0) {
        int rowI = p / 1280, w = p % 1280;
        int col = w >> 1, par = w & 1;
        int chunk = rowI >> 3, rr = rowI & 7;
        int k = chunk * 16 + (rr >> 2) * 8 + (rr & 3) * 2 + par;
        int m = col / 160, cc = col % 160;
        float v = 0.f;
        if (k < 300 && cc < 150) {
            const float* W = (m == 0) ? Wix : (m == 1) ? Wux : (m == 2) ? Wox : Wfx;
            v = W[k * 150 + cc];
        }
        g_Wxp[p] = __float2half_rn(v);
    } else if (p < T1) {
        int t = p - T0;
        int rowI = t / 1280, w = t % 1280;
        int col = w >> 1, par = w & 1;
        int chunk = rowI >> 3, rr = rowI & 7;
        int k = chunk * 16 + (rr >> 2) * 8 + (rr & 3) * 2 + par;
        int m = col / 160, cc = col % 160;
        float v = 0.f;
        if (k < 150 && cc < 150) {
            const float* W = (m == 0) ? Wih : (m == 1) ? Wuh : (m == 2) ? Woh : Wfh;
            v = W[k * 150 + cc];
        }
        g_Whp[t] = __float2half_rn(v);
    } else if (p < T2) {
        int t = p - T1;
        int k = t / 640, c = t % 640, m = c / 160, cc = c % 160;
        float v = 0.f;
        if (k < 150 && cc < 150) {
            const float* W = (m == 0) ? Wih : (m == 1) ? Wuh : (m == 2) ? Woh : Wfh;
            v = W[k * 150 + cc];
        }
        g_Wh2[t] = v;
    } else if (p < T3) {
        int c = p - T2, m = c / 160, cc = c % 160;
        float v = 0.f;
        if (cc < 150) {
            const float* b = (m == 0) ? bix : (m == 1) ? bux : (m == 2) ? box_ : bfx;
            v = b[cc];
        }
        g_bx[c] = v;
    } else {
        int c = p - T3, m = c / 160, cc = c % 160;
        float v = 0.f;
        if (cc < 150) {
            const float* b = (m == 0) ? bih : (m == 1) ? buh : (m == 2) ? boh : bfh;
            v = b[cc];
        }
        g_bh[c] = v;
    }
}

// =================== fp16 mma GEMM body: BK=32 stages, 3-stage cp.async =======
// BM=128, BN=160, 256 thr = 8 warps (2m x 4n), warp tile 64x40.
// Stage = 18944 B: A 2x4096 B + B 2x(8 rows x 672 B). 40 MMA/warp per sync pair.
template<bool BIAS>
__device__ __forceinline__ void gemm_body(
    const __half* __restrict__ At0,   // tiled A rows (chunk stride 2048 halves)
    const __half* __restrict__ Bp, int col0,
    __half* __restrict__ C, int ldc,
    const float* __restrict__ bias,
    int npair, int m0, int colblk, char* smb)
{
    const uint32_t sbase = (uint32_t)__cvta_generic_to_shared(smb);
    const int STGB = 18944;

    const int tid    = threadIdx.x;
    const int lane   = tid & 31;
    const int wid    = tid >> 5;
    const int m_warp = (wid >> 2) * 64;
    const int n_warp = (wid & 3) * 40;
    const int bcol0  = col0 + colblk;
    const int c4     = lane & 3;
    const int q      = lane >> 2;

    float acc[4][5][4];
#pragma unroll
    for (int i = 0; i < 4; i++)
#pragma unroll
        for (int j = 0; j < 5; j++)
#pragma unroll
            for (int p = 0; p < 4; p++) acc[i][j][p] = 0.0f;

    auto issue = [&](int st, int pr) {
        if (pr < npair) {
            const uint32_t dbase = sbase + st * STGB;
            const __half* Ac = At0 + (size_t)(2 * pr) * 2048;
            cp16(dbase + tid * 16, Ac + tid * 8);
            cp16(dbase + 4096 + tid * 16, Ac + 2048 + tid * 8);
            const __half* Bt = Bp + (size_t)(2 * pr) * 10240 + (size_t)bcol0 * 2;
#pragma unroll
            for (int e = 0; e < 3; e++) {
                int id = tid + e * 256;
                if (id < 640) {
                    int cch = id >> 9 ? 1 : (id >= 320 ? 1 : 0);
                    cch = id / 320;
                    int w = id - cch * 320;
                    int r = w / 40, o = w - r * 40;
                    cp16(dbase + 8192 + cch * 5376 + r * 672 + o * 16,
                         Bt + (size_t)cch * 10240 + r * 1280 + o * 8);
                }
            }
        }
        CP_COMMIT();
    };

    issue(0, 0);
    issue(1, 1);
    issue(2, 2);

    int st = 0;
    for (int pr = 0; pr < npair; pr++) {
        CP_WAIT2();
        __syncthreads();
#pragma unroll
        for (int cch = 0; cch < 2; cch++) {
            const uint32_t* Au = (const uint32_t*)(smb + (size_t)st * STGB + cch * 4096);
            const uint32_t* Bu = (const uint32_t*)(smb + (size_t)st * STGB + 8192 + cch * 5376);

            unsigned b[5][2];
#pragma unroll
            for (int j = 0; j < 5; j++) {
                int col = n_warp + q + 8 * j;
                b[j][0] = Bu[c4 * 168 + col];
                b[j][1] = Bu[(4 + c4) * 168 + col];
            }
#pragma unroll
            for (int i = 0; i < 4; i++) {
                int m1 = m_warp + 16 * i + q;
                unsigned a[4];
                a[0] = Au[m1 * 4 + c4];
                a[1] = Au[(m1 + 8) * 4 + c4];
                a[2] = Au[(128 + m1) * 4 + c4];
                a[3] = Au[(128 + m1 + 8) * 4 + c4];
#pragma unroll
                for (int j = 0; j < 5; j++) mma16(acc[i][j], a, b[j]);
            }
        }
        __syncthreads();
        issue(st, pr + 3);
        st = (st == 2) ? 0 : st + 1;
    }

    const int r0 = m0 + m_warp + q;
    const int cl = n_warp + c4 * 2;
#pragma unroll
    for (int i = 0; i < 4; i++) {
#pragma unroll
        for (int h = 0; h < 2; h++) {
            int r = r0 + 16 * i + 8 * h;
            __half* crow = C + (size_t)r * ldc + colblk;
#pragma unroll
            for (int j = 0; j < 5; j++) {
                int c = cl + 8 * j;
                float v0 = acc[i][j][2 * h], v1 = acc[i][j][2 * h + 1];
                if (BIAS) {
                    v0 += bias[bcol0 + c];
                    v1 += bias[bcol0 + c + 1];
                }
                *(__half2*)(crow + c) = __floats2half2_rn(v0, v1);
            }
        }
    }
}

// ---- X projection, single launch: grid (4, 683); leaf rows skip f-gate ------
__global__ __launch_bounds__(256, 2)
void gemm_x(const __half* __restrict__ A2, const __half* __restrict__ Bp,
            __half* __restrict__ C, const float* __restrict__ bias)
{
    extern __shared__ __align__(16) char smb[];
    const int cb = blockIdx.x, rb = blockIdx.y;
    if (cb == 3 && rb < 512) return;   // leaves don't need the f-gate block
    gemm_body<true>(A2 + (size_t)rb * 20 * 2048, Bp, 0, C, 640, bias,
                    10, rb * 128, cb * 160, smb);
}

// ---- combined P + F GEMM for one level: grid (7, n/128) ---------------------
__global__ __launch_bounds__(256, 2)
void gemm_pf(const __half* __restrict__ Ap, const __half* __restrict__ Af,
             const __half* __restrict__ Bp,
             __half* __restrict__ Cp, __half* __restrict__ Cf)
{
    extern __shared__ __align__(16) char smb[];
    const int x = blockIdx.x, y = blockIdx.y;
    if (x < 3) {
        gemm_body<false>(Ap + (size_t)y * 10 * 2048, Bp, 0, Cp, 480, nullptr,
                         5, y * 128, x * 160, smb);
    } else {
        int rb = y * 4 + (x - 3);
        gemm_body<false>(Af + (size_t)rb * 10 * 2048, Bp, 480, Cf, 160, nullptr,
                         5, rb * 128, 0, smb);
    }
}

// =================== leaves: gates + child-sum fused ===========================
__global__ void leaf_kernel(float* __restrict__ out)
{
    int idx = blockIdx.x * blockDim.x + threadIdx.x;
    if (idx >= 16384 * 80) return;
    int pp = idx / 80, j2 = (idx - pp * 80) * 2;
    if (j2 >= 150) {
        __half2 z = __floats2half2_rn(0.f, 0.f);
#pragma unroll
        for (int s = 0; s < 4; s++)
            *(__half2*)(g_H2 + hpos(4 * pp + s, j2)) = z;
        *(__half2*)(g_HS2 + hpos(pp, j2)) = z;
        return;
    }
    float bi0 = g_bh[j2],       bi1 = g_bh[j2 + 1];
    float bu0 = g_bh[160 + j2], bu1 = g_bh[161 + j2];
    float bo0 = g_bh[320 + j2], bo1 = g_bh[321 + j2];
    float hsx = 0.f, hsy = 0.f;
#pragma unroll
    for (int s = 0; s < 4; s++) {
        int p = 4 * pp + s;
        const __half* Xr = g_X + (size_t)p * 640;
        float2 xi = __half22float2(*(const __half2*)(Xr + j2));
        float2 xu = __half22float2(*(const __half2*)(Xr + 160 + j2));
        float2 xo = __half22float2(*(const __half2*)(Xr + 320 + j2));
        float2 cv, hv;
        {
            float ig = sigf(xi.x + bi0);
            float ug = tanh_fast(xu.x + bu0);
            float og = sigf(xo.x + bo0);
            cv.x = ig * ug;
            hv.x = og * tanh_fast(cv.x);
        }
        {
            float ig = sigf(xi.y + bi1);
            float ug = tanh_fast(xu.y + bu1);
            float og = sigf(xo.y + bo1);
            cv.y = ig * ug;
            hv.y = og * tanh_fast(cv.y);
        }
        *(float2*)(g_C + (size_t)p * 150 + j2) = cv;
        *(float2*)(out + (size_t)p * 150 + j2) = hv;
        __half2 hh = __floats2half2_rn(hv.x, hv.y);
        *(__half2*)(g_H2 + hpos(p, j2)) = hh;
        float2 hr = __half22float2(hh);
        hsx += hr.x;
        hsy += hr.y;
    }
    *(__half2*)(g_HS2 + hpos(pp, j2)) = __floats2half2_rn(hsx, hsy);
}

// =================== internal level: gates + fc + next-level child-sum ========
__global__ void level_kernel(float* __restrict__ out, int off_p, int off_c,
                             int n, int writeHS)
{
    int idx = blockIdx.x * blockDim.x + threadIdx.x;
    if (idx >= (n >> 2) * 80) return;
    int pn = idx / 80, j2 = (idx - pn * 80) * 2;
    if (j2 >= 150) {
        __half2 z = __floats2half2_rn(0.f, 0.f);
#pragma unroll
        for (int s = 0; s < 4; s++)
            *(__half2*)(g_H2 + hpos(off_p + 4 * pn + s, j2)) = z;
        if (writeHS) *(__half2*)(g_HS2 + hpos(pn, j2)) = z;
        return;
    }
    float bi0 = g_bh[j2],       bi1 = g_bh[j2 + 1];
    float bu0 = g_bh[160 + j2], bu1 = g_bh[161 + j2];
    float bo0 = g_bh[320 + j2], bo1 = g_bh[321 + j2];
    float bf0 = g_bh[480 + j2], bf1 = g_bh[481 + j2];
    float hsx = 0.f, hsy = 0.f;
#pragma unroll
    for (int s = 0; s < 4; s++) {
        int p = 4 * pn + s;
        int g = off_p + p;
        const __half* Xr = g_X + (size_t)g * 640;
        const __half* Pr = g_P + (size_t)p * 480;
        float2 xi = __half22float2(*(const __half2*)(Xr + j2));
        float2 xu = __half22float2(*(const __half2*)(Xr + 160 + j2));
        float2 xo = __half22float2(*(const __half2*)(Xr + 320 + j2));
        float2 xf = __half22float2(*(const __half2*)(Xr + 480 + j2));
        float2 pi = __half22float2(*(const __half2*)(Pr + j2));
        float2 pu = __half22float2(*(const __half2*)(Pr + 160 + j2));
        float2 po = __half22float2(*(const __half2*)(Pr + 320 + j2));

        float igx = sigf(xi.x + pi.x + bi0);
        float igy = sigf(xi.y + pi.y + bi1);
        float ugx = tanh_fast(xu.x + pu.x + bu0);
        float ugy = tanh_fast(xu.y + pu.y + bu1);
        float ogx = sigf(xo.x + po.x + bo0);
        float ogy = sigf(xo.y + po.y + bo1);
        float xfx = xf.x + bf0;
        float xfy = xf.y + bf1;

        float fcx = 0.f, fcy = 0.f;
#pragma unroll
        for (int k = 0; k < 4; k++) {
            int cl = 4 * p + k;
            float2 fv = __half22float2(*(const __half2*)(g_F + (size_t)cl * 160 + j2));
            float2 cc = *(const float2*)(g_C + (size_t)(off_c + cl) * 150 + j2);
            fcx = fmaf(sigf(xfx + fv.x), cc.x, fcx);
            fcy = fmaf(sigf(xfy + fv.y), cc.y, fcy);
        }
        float cx = fmaf(igx, ugx, fcx);
        float cy = fmaf(igy, ugy, fcy);
        *(float2*)(g_C + (size_t)g * 150 + j2) = make_float2(cx, cy);
        float hx = ogx * tanh_fast(cx);
        float hy = ogy * tanh_fast(cy);
        *(float2*)(out + (size_t)g * 150 + j2) = make_float2(hx, hy);
        __half2 hh = __floats2half2_rn(hx, hy);
        *(__half2*)(g_H2 + hpos(g, j2)) = hh;
        float2 hr = __half22float2(hh);
        hsx += hr.x;
        hsy += hr.y;
    }
    if (writeHS)
        *(__half2*)(g_HS2 + hpos(pn, j2)) = __floats2half2_rn(hsx, hsy);
}

// =================== fused small level (d=4..8, n<=256) ========================
__global__ __launch_bounds__(160)
void small_level_kernel(float* __restrict__ out, int off_p, int off_c)
{
    int p = blockIdx.x, j = threadIdx.x;
    __shared__ float hs[160];
    __shared__ float hch[4][160];
    int g = off_p + p;
    float h0 = __half2float(g_H2[hpos(off_c + 4 * p + 0, j)]);
    float h1 = __half2float(g_H2[hpos(off_c + 4 * p + 1, j)]);
    float h2 = __half2float(g_H2[hpos(off_c + 4 * p + 2, j)]);
    float h3 = __half2float(g_H2[hpos(off_c + 4 * p + 3, j)]);
    hch[0][j] = h0; hch[1][j] = h1; hch[2][j] = h2; hch[3][j] = h3;
    hs[j] = h0 + h1 + h2 + h3;
    __syncthreads();

    float di = 0.f, du = 0.f, dog = 0.f;
    float df0 = 0.f, df1 = 0.f, df2 = 0.f, df3 = 0.f;
#pragma unroll 4
    for (int m = 0; m < 160; m++) {
        float hm = hs[m];
        const float* wrow = g_Wh2 + m * 640;
        di  = fmaf(hm, wrow[j], di);
        du  = fmaf(hm, wrow[160 + j], du);
        dog = fmaf(hm, wrow[320 + j], dog);
        float wf = wrow[480 + j];
        df0 = fmaf(hch[0][m], wf, df0);
        df1 = fmaf(hch[1][m], wf, df1);
        df2 = fmaf(hch[2][m], wf, df2);
        df3 = fmaf(hch[3][m], wf, df3);
    }
    if (j < 150) {
        const __half* Xr = g_X + (size_t)g * 640;
        float ig = sigf(__half2float(Xr[j]) + di + g_bh[j]);
        float ug = tanh_fast(__half2float(Xr[160 + j]) + du + g_bh[160 + j]);
        float og = sigf(__half2float(Xr[320 + j]) + dog + g_bh[320 + j]);
        float xf = __half2float(Xr[480 + j]) + g_bh[480 + j];
        float fc = sigf(xf + df0) * g_C[(size_t)(off_c + 4 * p + 0) * 150 + j]
                 + sigf(xf + df1) * g_C[(size_t)(off_c + 4 * p + 1) * 150 + j]
                 + sigf(xf + df2) * g_C[(size_t)(off_c + 4 * p + 2) * 150 + j]
                 + sigf(xf + df3) * g_C[(size_t)(off_c + 4 * p + 3) * 150 + j];
        float c = fmaf(ig, ug, fc);
        g_C[(size_t)g * 150 + j] = c;
        float h = og * tanh_fast(c);
        out[(size_t)g * 150 + j] = h;
        g_H2[hpos(g, j)] = __float2half_rn(h);
    } else {
        g_H2[hpos(g, j)] = __float2half_rn(0.f);
    }
}

// =================== host orchestration ========================================
extern "C" void kernel_launch(void* const* d_in, const int* in_sizes, int n_in,
                              void* d_out, int out_size)
{
    const float* embs = (const float*)d_in[0];
    const float* Wix = (const float*)d_in[1];  const float* bix = (const float*)d_in[2];
    const float* Wfx = (const float*)d_in[3];  const float* bfx = (const float*)d_in[4];
    const float* Wux = (const float*)d_in[5];  const float* bux = (const float*)d_in[6];
    const float* Wox = (const float*)d_in[7];  const float* box_ = (const float*)d_in[8];
    const float* Wih = (const float*)d_in[9];  const float* bih = (const float*)d_in[10];
    const float* Wfh = (const float*)d_in[11]; const float* bfh = (const float*)d_in[12];
    const float* Wuh = (const float*)d_in[13]; const float* buh = (const float*)d_in[14];
    const float* Woh = (const float*)d_in[15]; const float* boh = (const float*)d_in[16];
    float* out = (float*)d_out;

    __half *pE2, *pX, *pH2, *pHS2, *pWxp, *pWhp, *pP, *pF;
    float *pbx;
    cudaGetSymbolAddress((void**)&pE2,  g_E2);
    cudaGetSymbolAddress((void**)&pX,   g_X);
    cudaGetSymbolAddress((void**)&pH2,  g_H2);
    cudaGetSymbolAddress((void**)&pHS2, g_HS2);
    cudaGetSymbolAddress((void**)&pWxp, g_Wxp);
    cudaGetSymbolAddress((void**)&pWhp, g_Whp);
    cudaGetSymbolAddress((void**)&pbx,  g_bx);
    cudaGetSymbolAddress((void**)&pP,   g_P);
    cudaGetSymbolAddress((void**)&pF,   g_F);

    static const int SIZES[9] = {65536, 16384, 4096, 1024, 256, 64, 16, 4, 1};
    static const int OFF[9]   = {0, 65536, 81920, 86016, 87040, 87296, 87360, 87376, 87380};
    const int SMEM = 3 * 18944;   // 56832 B

    cudaFuncSetAttribute(gemm_x,
                         cudaFuncAttributeMaxDynamicSharedMemorySize, SMEM);
    cudaFuncSetAttribute(gemm_pf,
                         cudaFuncAttributeMaxDynamicSharedMemorySize, SMEM);

    // 1. prep: embs round+tile (20 chunks), weight pack (one launch)
    {
        const int TOT = 683 * 20 * 1024 + (20 * 10240 + 10 * 10240 + 160 * 640 + 1280);
        prep_kernel<<<(TOT + 255) / 256, 256>>>(embs,
            Wix, bix, Wfx, bfx, Wux, bux, Wox, box_,
            Wih, bih, Wfh, bfh, Wuh, buh, Woh, boh);
    }

    // 2. X projections, one launch (leaf row-blocks skip the f-gate column)
    {
        dim3 grid(4, 683);
        gemm_x<<<grid, 256, SMEM>>>(pE2, pWxp, pX, pbx);
    }

    // 3. leaves (+ child-sum for level 1)
    leaf_kernel<<<(16384 * 80 + 255) / 256, 256>>>(out);

    // 4. levels 1..3: one P+F GEMM launch, one level(+hsum) launch each
    for (int d = 1; d <= 3; d++) {
        int n = SIZES[d];
        {
            dim3 grid(7, n / 128);
            gemm_pf<<<grid, 256, SMEM>>>(pHS2, pH2 + (size_t)OFF[d - 1] * 160,
                                         pWhp, pP, pF);
        }
        level_kernel<<<((n >> 2) * 80 + 255) / 256, 256>>>(out, OFF[d], OFF[d - 1],
                                                           n, d < 3 ? 1 : 0);
    }

    // 5. levels 4..8: fused fp32 kernels (n = 256, 64, 16, 4, 1)
    for (int d = 4; d <= 8; d++)
        small_level_kernel<<<SIZES[d], 160>>>(out, OFF[d], OFF[d - 1]);
}